// round 1
// baseline (speedup 1.0000x reference)
#include <cuda_runtime.h>
#include <cstdint>

#define KDIM 512
#define FDIM 512
#define BM   128
#define XPITCH 528   // 512 + 16 bytes pad -> conflict-free fragment loads

__device__ int8_t g_wq[FDIM * KDIM];   // [F][K] (B col-major for mma row.col)
__device__ float  g_inv[FDIM];         // 1 / (a_scale * w_scale[j])

// ---------------------------------------------------------------------------
// Weight prequant: 16 blocks x 256 threads, each block handles 32 columns.
// ---------------------------------------------------------------------------
__global__ void quant_w_kernel(const float* __restrict__ kernel) {
    extern __shared__ float sm[];            // [512][33] floats
    __shared__ float red[8][32];
    __shared__ float sscale[32];
    const int j0 = blockIdx.x * 32;
    const int t  = threadIdx.x;

    // coalesced load of 512 x 32 column slab into smem (padded pitch 33)
    #pragma unroll 4
    for (int i = 0; i < 64; ++i) {
        int idx = i * 256 + t;
        int k = idx >> 5, c = idx & 31;
        sm[k * 33 + c] = kernel[k * FDIM + j0 + c];
    }
    __syncthreads();

    // per-column abs-max
    {
        int c = t & 31, kr = t >> 5;
        float m = 0.f;
        #pragma unroll 8
        for (int i = 0; i < 64; ++i)
            m = fmaxf(m, fabsf(sm[(kr + i * 8) * 33 + c]));
        red[kr][c] = m;
    }
    __syncthreads();
    if (t < 32) {
        float m = red[0][t];
        #pragma unroll
        for (int r = 1; r < 8; ++r) m = fmaxf(m, red[r][t]);
        float s = __fdiv_rn(127.0f, fmaxf(m, 1e-7f));
        sscale[t] = s;
        const float A_SCALE = 127.0f / 3.0f;
        g_inv[j0 + t] = __fdiv_rn(1.0f, __fmul_rn(A_SCALE, s));
    }
    __syncthreads();

    // quantize + write: warp w -> cols w*4..w*4+3, lanes stride k (coalesced int writes)
    const int w = t >> 5, lane = t & 31;
    for (int cc = 0; cc < 4; ++cc) {
        int c = w * 4 + cc;
        float s = sscale[c];
        #pragma unroll
        for (int i = 0; i < 4; ++i) {
            int kb = i * 128 + lane * 4;
            int q[4];
            #pragma unroll
            for (int jj = 0; jj < 4; ++jj) {
                float v = __fmul_rn(sm[(kb + jj) * 33 + c], s);
                int qi = __float2int_rn(v);
                qi = max(-127, min(127, qi));
                q[jj] = qi;
            }
            unsigned pk = (q[0] & 0xff) | ((q[1] & 0xff) << 8) |
                          ((q[2] & 0xff) << 16) | ((unsigned)(q[3] & 0xff) << 24);
            *(unsigned*)&g_wq[(size_t)(j0 + c) * KDIM + kb] = pk;
        }
    }
}

// ---------------------------------------------------------------------------
// Fused quantize-x + int8 GEMM. 256 threads (8 warps: 4 M x 2 N), BM=128 rows
// per CTA, 4 N-chunks of 128 cols. mma.sync.m16n8k32.s8 with int32 accum
// (bit-exact vs reference: |partial sums| < 2^24).
// ---------------------------------------------------------------------------
__global__ void gemm_kernel(const float* __restrict__ x,
                            const float* __restrict__ bias,
                            float* __restrict__ y) {
    extern __shared__ char smem[];
    int8_t* xs = (int8_t*)smem;               // [128][XPITCH]
    int8_t* ws = (int8_t*)(smem + BM * XPITCH); // [128][XPITCH]

    const int t  = threadIdx.x;
    const int r0 = blockIdx.x * BM;
    const float A_SCALE = 127.0f / 3.0f;

    // ---- load + quantize x tile: 128 x 512 fp32 -> int8 smem ----
    #pragma unroll 4
    for (int i = 0; i < 64; ++i) {
        int idx = i * 256 + t;        // float4 index within tile (16384 total)
        int row = idx >> 7;
        int c4  = idx & 127;
        float4 v = __ldg((const float4*)(x + (size_t)(r0 + row) * KDIM) + c4);
        int q0 = max(-127, min(127, __float2int_rn(__fmul_rn(v.x, A_SCALE))));
        int q1 = max(-127, min(127, __float2int_rn(__fmul_rn(v.y, A_SCALE))));
        int q2 = max(-127, min(127, __float2int_rn(__fmul_rn(v.z, A_SCALE))));
        int q3 = max(-127, min(127, __float2int_rn(__fmul_rn(v.w, A_SCALE))));
        unsigned pk = (q0 & 0xff) | ((q1 & 0xff) << 8) |
                      ((q2 & 0xff) << 16) | ((unsigned)(q3 & 0xff) << 24);
        *(unsigned*)&xs[row * XPITCH + c4 * 4] = pk;
    }

    const int warp = t >> 5, lane = t & 31;
    const int wm = warp >> 1, wn = warp & 1;
    const int grp = lane >> 2, qid = lane & 3;

    for (int nb = 0; nb < 4; ++nb) {
        __syncthreads();   // x stores visible / previous chunk reads done
        // ---- stage W chunk [128][512] int8 from L2 ----
        #pragma unroll 4
        for (int i = 0; i < 16; ++i) {
            int idx = i * 256 + t;    // int4 index (4096 total)
            int n = idx >> 5, c16 = idx & 31;
            int4 v = *((const int4*)(g_wq + ((size_t)(nb * 128 + n) << 9)) + c16);
            *(int4*)&ws[n * XPITCH + c16 * 16] = v;
        }
        __syncthreads();

        int acc[2][8][4];
        #pragma unroll
        for (int mt = 0; mt < 2; ++mt)
            #pragma unroll
            for (int nt = 0; nt < 8; ++nt)
                #pragma unroll
                for (int r = 0; r < 4; ++r) acc[mt][nt][r] = 0;

        for (int ks = 0; ks < 16; ++ks) {
            unsigned a[2][4];
            #pragma unroll
            for (int mt = 0; mt < 2; ++mt) {
                const int8_t* p = &xs[(wm * 32 + mt * 16 + grp) * XPITCH + ks * 32 + qid * 4];
                a[mt][0] = *(const unsigned*)p;
                a[mt][1] = *(const unsigned*)(p + 8 * XPITCH);
                a[mt][2] = *(const unsigned*)(p + 16);
                a[mt][3] = *(const unsigned*)(p + 8 * XPITCH + 16);
            }
            unsigned b[8][2];
            #pragma unroll
            for (int nt = 0; nt < 8; ++nt) {
                const int8_t* p = &ws[(wn * 64 + nt * 8 + grp) * XPITCH + ks * 32 + qid * 4];
                b[nt][0] = *(const unsigned*)p;
                b[nt][1] = *(const unsigned*)(p + 16);
            }
            #pragma unroll
            for (int mt = 0; mt < 2; ++mt)
                #pragma unroll
                for (int nt = 0; nt < 8; ++nt)
                    asm volatile(
                        "mma.sync.aligned.m16n8k32.row.col.s32.s8.s8.s32 "
                        "{%0,%1,%2,%3},{%4,%5,%6,%7},{%8,%9},{%0,%1,%2,%3};\n"
                        : "+r"(acc[mt][nt][0]), "+r"(acc[mt][nt][1]),
                          "+r"(acc[mt][nt][2]), "+r"(acc[mt][nt][3])
                        : "r"(a[mt][0]), "r"(a[mt][1]), "r"(a[mt][2]), "r"(a[mt][3]),
                          "r"(b[nt][0]), "r"(b[nt][1]));
        }

        // ---- epilogue: dequant + bias, float2 stores ----
        #pragma unroll
        for (int mt = 0; mt < 2; ++mt) {
            int row = r0 + wm * 32 + mt * 16 + grp;
            #pragma unroll
            for (int nt = 0; nt < 8; ++nt) {
                int col = nb * 128 + wn * 64 + nt * 8 + qid * 2;
                float i0 = g_inv[col],  i1 = g_inv[col + 1];
                float b0 = __ldg(bias + col), b1 = __ldg(bias + col + 1);
                float2 v0, v1;
                v0.x = (float)acc[mt][nt][0] * i0 + b0;
                v0.y = (float)acc[mt][nt][1] * i1 + b1;
                v1.x = (float)acc[mt][nt][2] * i0 + b0;
                v1.y = (float)acc[mt][nt][3] * i1 + b1;
                *(float2*)&y[(size_t)row * FDIM + col] = v0;
                *(float2*)&y[(size_t)(row + 8) * FDIM + col] = v1;
            }
        }
    }
}

// ---------------------------------------------------------------------------
extern "C" void kernel_launch(void* const* d_in, const int* in_sizes, int n_in,
                              void* d_out, int out_size) {
    const float* x    = (const float*)d_in[0];
    const float* kern = (const float*)d_in[1];
    const float* bias = (const float*)d_in[2];
    float* y = (float*)d_out;
    const int nrows = in_sizes[0] / KDIM;

    cudaFuncSetAttribute(quant_w_kernel,
                         cudaFuncAttributeMaxDynamicSharedMemorySize, 512 * 33 * 4);
    cudaFuncSetAttribute(gemm_kernel,
                         cudaFuncAttributeMaxDynamicSharedMemorySize, 2 * BM * XPITCH);

    quant_w_kernel<<<FDIM / 32, 256, 512 * 33 * 4>>>(kern);
    gemm_kernel<<<nrows / BM, 256, 2 * BM * XPITCH>>>(x, bias, y);
}

// round 4
// speedup vs baseline: 1.2177x; 1.2177x over previous
#include <cuda_runtime.h>
#include <cstdint>

#define KDIM 512
#define FDIM 512
#define BM   128
#define BN   64                 // N-chunk per iteration (8 chunks)

// smem layout (bytes)
#define SM_X    0               // 128 x 512 int8, XOR-swizzled rows
#define SM_W    65536           // 64 x 512 int8, XOR-swizzled rows
#define SM_INV  98304           // 512 floats
#define SM_BIAS 100352          // 512 floats
#define SMEM_TOTAL 102400       // 100 KB -> 2 CTAs/SM

__device__ __align__(16) int8_t g_wq[FDIM * KDIM];   // [F][K]
__device__ float g_inv[FDIM];

__device__ __forceinline__ uint32_t smem_u32(const void* p) {
    uint32_t a;
    asm("{ .reg .u64 t; cvta.to.shared.u64 t, %1; cvt.u32.u64 %0, t; }" : "=r"(a) : "l"(p));
    return a;
}
__device__ __forceinline__ void cp_async16(uint32_t dst, const void* src) {
    asm volatile("cp.async.cg.shared.global [%0], [%1], 16;" :: "r"(dst), "l"(src));
}

// ---------------------------------------------------------------------------
// Weight prequant: per-output-column abs-max -> int8 g_wq[F][K], plus
// fused dequant factor g_inv[j] = 1/(a_scale * w_scale[j]).
// ---------------------------------------------------------------------------
__global__ void quant_w_kernel(const float* __restrict__ kernel) {
    extern __shared__ float sm[];            // [512][33]
    __shared__ float red[8][32];
    __shared__ float sscale[32];
    const int j0 = blockIdx.x * 32;
    const int t  = threadIdx.x;

    #pragma unroll 4
    for (int i = 0; i < 64; ++i) {
        int idx = i * 256 + t;
        int k = idx >> 5, c = idx & 31;
        sm[k * 33 + c] = kernel[k * FDIM + j0 + c];
    }
    __syncthreads();
    {
        int c = t & 31, kr = t >> 5;
        float m = 0.f;
        #pragma unroll 8
        for (int i = 0; i < 64; ++i)
            m = fmaxf(m, fabsf(sm[(kr + i * 8) * 33 + c]));
        red[kr][c] = m;
    }
    __syncthreads();
    if (t < 32) {
        float m = red[0][t];
        #pragma unroll
        for (int r = 1; r < 8; ++r) m = fmaxf(m, red[r][t]);
        float s = __fdiv_rn(127.0f, fmaxf(m, 1e-7f));
        sscale[t] = s;
        const float A_SCALE = 127.0f / 3.0f;
        g_inv[j0 + t] = __fdiv_rn(1.0f, __fmul_rn(A_SCALE, s));
    }
    __syncthreads();

    const int w = t >> 5, lane = t & 31;
    for (int cc = 0; cc < 4; ++cc) {
        int c = w * 4 + cc;
        float s = sscale[c];
        #pragma unroll
        for (int i = 0; i < 4; ++i) {
            int kb = i * 128 + lane * 4;
            int q[4];
            #pragma unroll
            for (int jj = 0; jj < 4; ++jj) {
                float v = __fmul_rn(sm[(kb + jj) * 33 + c], s);
                int qi = __float2int_rn(v);
                q[jj] = max(-127, min(127, qi));
            }
            unsigned pk = (q[0] & 0xff) | ((q[1] & 0xff) << 8) |
                          ((q[2] & 0xff) << 16) | ((unsigned)(q[3] & 0xff) << 24);
            *(unsigned*)&g_wq[(size_t)(j0 + c) * KDIM + kb] = pk;
        }
    }
}

// ---------------------------------------------------------------------------
// Fused quantize-x + int8 legacy-MMA GEMM, 2 CTAs/SM, cp.async W staging.
// ---------------------------------------------------------------------------
__device__ __forceinline__ void load_w_async(uint32_t ws_u, int nb, int t) {
    const int8_t* base = g_wq + (size_t)nb * BN * KDIM;
    #pragma unroll
    for (int i = 0; i < 8; ++i) {
        int idx = i * 256 + t;               // 2048 16B-chunks
        int n = idx >> 5, c16 = idx & 31;
        uint32_t dst = ws_u + n * KDIM + ((c16 * 16) ^ ((n & 7) << 4));
        cp_async16(dst, base + n * KDIM + c16 * 16);
    }
    asm volatile("cp.async.commit_group;" ::: "memory");
}

__global__ void __launch_bounds__(256, 2)
gemm_kernel(const float* __restrict__ x, const float* __restrict__ bias,
            float* __restrict__ y) {
    extern __shared__ char smem[];
    int8_t* xs = (int8_t*)(smem + SM_X);
    int8_t* ws = (int8_t*)(smem + SM_W);
    float* sinv  = (float*)(smem + SM_INV);
    float* sbias = (float*)(smem + SM_BIAS);

    const int t  = threadIdx.x;
    const int r0 = blockIdx.x * BM;
    const uint32_t ws_u = smem_u32(ws);

    // kick off W chunk 0 first so it overlaps the x-quant phase
    load_w_async(ws_u, 0, t);

    for (int i = t; i < FDIM; i += 256) {
        sinv[i]  = g_inv[i];
        sbias[i] = bias[i];
    }

    // quantize x tile: 128 x 512 fp32 -> int8, XOR-swizzled rows
    const float A_SCALE = 127.0f / 3.0f;
    #pragma unroll 2
    for (int i = 0; i < 16; ++i) {
        int idx = i * 256 + t;               // 16B-chunk id (4096 total)
        int row = idx >> 5, c16 = idx & 31;
        const float4* src = (const float4*)(x + (size_t)(r0 + row) * KDIM + c16 * 16);
        int pk[4];
        #pragma unroll
        for (int j = 0; j < 4; ++j) {
            float4 v = __ldg(src + j);
            int q0 = max(-127, min(127, __float2int_rn(__fmul_rn(v.x, A_SCALE))));
            int q1 = max(-127, min(127, __float2int_rn(__fmul_rn(v.y, A_SCALE))));
            int q2 = max(-127, min(127, __float2int_rn(__fmul_rn(v.z, A_SCALE))));
            int q3 = max(-127, min(127, __float2int_rn(__fmul_rn(v.w, A_SCALE))));
            pk[j] = (q0 & 0xff) | ((q1 & 0xff) << 8) |
                    ((q2 & 0xff) << 16) | ((unsigned)(q3 & 0xff) << 24);
        }
        *(int4*)&xs[row * KDIM + ((c16 * 16) ^ ((row & 7) << 4))] =
            make_int4(pk[0], pk[1], pk[2], pk[3]);
    }

    asm volatile("cp.async.wait_group 0;" ::: "memory");
    __syncthreads();

    const int warp = t >> 5, lane = t & 31;
    const int wm = warp >> 1, wn = warp & 1;     // 4 M-warps x 2 N-warps
    const int grp = lane >> 2, qid = lane & 3;
    const int g4 = grp << 4;

    // fragment row base pointers (row & 7 == grp for all of them)
    const int8_t* xr0 = xs + (wm * 32 + grp) * KDIM;          // mt=0 rows grp, grp+8
    const int8_t* xr1 = xr0 + 16 * KDIM;                      // mt=1
    const int8_t* wr  = ws + (wn * 32 + grp) * KDIM;          // nt rows step 8

    float* yr0 = y + (size_t)(r0 + wm * 32 + grp) * FDIM;

    for (int nb = 0; nb < 8; ++nb) {
        int acc[2][4][4];
        #pragma unroll
        for (int mt = 0; mt < 2; ++mt)
            #pragma unroll
            for (int nt = 0; nt < 4; ++nt)
                #pragma unroll
                for (int r = 0; r < 4; ++r) acc[mt][nt][r] = 0;

        #pragma unroll
        for (int ks = 0; ks < 16; ++ks) {
            const int c0 = (ks * 32 + qid * 4) ^ g4;
            const int c1 = (ks * 32 + qid * 4 + 16) ^ g4;
            unsigned a[2][4], b[4][2];
            a[0][0] = *(const unsigned*)(xr0 + c0);
            a[0][1] = *(const unsigned*)(xr0 + 8 * KDIM + c0);
            a[0][2] = *(const unsigned*)(xr0 + c1);
            a[0][3] = *(const unsigned*)(xr0 + 8 * KDIM + c1);
            a[1][0] = *(const unsigned*)(xr1 + c0);
            a[1][1] = *(const unsigned*)(xr1 + 8 * KDIM + c0);
            a[1][2] = *(const unsigned*)(xr1 + c1);
            a[1][3] = *(const unsigned*)(xr1 + 8 * KDIM + c1);
            #pragma unroll
            for (int nt = 0; nt < 4; ++nt) {
                b[nt][0] = *(const unsigned*)(wr + nt * 8 * KDIM + c0);
                b[nt][1] = *(const unsigned*)(wr + nt * 8 * KDIM + c1);
            }
            #pragma unroll
            for (int mt = 0; mt < 2; ++mt)
                #pragma unroll
                for (int nt = 0; nt < 4; ++nt)
                    asm volatile(
                        "mma.sync.aligned.m16n8k32.row.col.s32.s8.s8.s32 "
                        "{%0,%1,%2,%3},{%4,%5,%6,%7},{%8,%9},{%0,%1,%2,%3};\n"
                        : "+r"(acc[mt][nt][0]), "+r"(acc[mt][nt][1]),
                          "+r"(acc[mt][nt][2]), "+r"(acc[mt][nt][3])
                        : "r"(a[mt][0]), "r"(a[mt][1]), "r"(a[mt][2]), "r"(a[mt][3]),
                          "r"(b[nt][0]), "r"(b[nt][1]));
        }

        __syncthreads();                      // all warps done reading ws
        if (nb < 7) load_w_async(ws_u, nb + 1, t);   // overlaps epilogue below

        // epilogue: dequant + bias, float2 stores (registers + gmem only)
        #pragma unroll
        for (int mt = 0; mt < 2; ++mt) {
            float* yr = yr0 + mt * 16 * FDIM;
            #pragma unroll
            for (int nt = 0; nt < 4; ++nt) {
                int col = nb * BN + wn * 32 + nt * 8 + qid * 2;
                float i0 = sinv[col], i1 = sinv[col + 1];
                float b0 = sbias[col], b1 = sbias[col + 1];
                float2 v0, v1;
                v0.x = (float)acc[mt][nt][0] * i0 + b0;
                v0.y = (float)acc[mt][nt][1] * i1 + b1;
                v1.x = (float)acc[mt][nt][2] * i0 + b0;
                v1.y = (float)acc[mt][nt][3] * i1 + b1;
                *(float2*)(yr + col) = v0;
                *(float2*)(yr + 8 * FDIM + col) = v1;
            }
        }

        if (nb < 7) {
            asm volatile("cp.async.wait_group 0;" ::: "memory");
            __syncthreads();
        }
    }
}

// ---------------------------------------------------------------------------
extern "C" void kernel_launch(void* const* d_in, const int* in_sizes, int n_in,
                              void* d_out, int out_size) {
    const float* x    = (const float*)d_in[0];
    const float* kern = (const float*)d_in[1];
    const float* bias = (const float*)d_in[2];
    float* y = (float*)d_out;
    const int nrows = in_sizes[0] / KDIM;

    cudaFuncSetAttribute(quant_w_kernel,
                         cudaFuncAttributeMaxDynamicSharedMemorySize, 512 * 33 * 4);
    cudaFuncSetAttribute(gemm_kernel,
                         cudaFuncAttributeMaxDynamicSharedMemorySize, SMEM_TOTAL);

    quant_w_kernel<<<FDIM / 32, 256, 512 * 33 * 4>>>(kern);
    gemm_kernel<<<nrows / BM, 256, SMEM_TOTAL>>>(x, bias, y);
}

// round 5
// speedup vs baseline: 1.2587x; 1.0337x over previous
#include <cuda_runtime.h>
#include <cstdint>

#define KDIM 512
#define FDIM 512
#define BM   128
#define BN   32                 // N-chunk per iteration (16 chunks)

// smem layout (bytes)
#define SM_X    0               // 128 x 512 int8, XOR-swizzled rows
#define SM_W    65536           // 2 x (32 x 512) int8 double buffer
#define SM_INV  98304           // 512 floats
#define SM_BIAS 100352          // 512 floats
#define SMEM_TOTAL 102400       // 100 KB -> 2 CTAs/SM

#define WBUF_BYTES (BN * KDIM)  // 16384

__device__ __align__(16) int8_t g_wq[FDIM * KDIM];   // [F][K]
__device__ float g_inv[FDIM];

__device__ __forceinline__ uint32_t smem_u32(const void* p) {
    uint32_t a;
    asm("{ .reg .u64 t; cvta.to.shared.u64 t, %1; cvt.u32.u64 %0, t; }" : "=r"(a) : "l"(p));
    return a;
}
__device__ __forceinline__ void cp_async16(uint32_t dst, const void* src) {
    asm volatile("cp.async.cg.shared.global [%0], [%1], 16;" :: "r"(dst), "l"(src));
}

// ---------------------------------------------------------------------------
// Weight prequant: 32 blocks x 256 threads, 16 output-cols per block.
// ---------------------------------------------------------------------------
__global__ void quant_w_kernel(const float* __restrict__ kernel) {
    __shared__ float sm[512 * 17];
    __shared__ float red[16][16];
    __shared__ float sscale[16];
    const int j0 = blockIdx.x * 16;
    const int t  = threadIdx.x;

    #pragma unroll 4
    for (int i = 0; i < 32; ++i) {
        int idx = i * 256 + t;
        int k = idx >> 4, c = idx & 15;
        sm[k * 17 + c] = kernel[k * FDIM + j0 + c];
    }
    __syncthreads();
    {
        int c = t & 15, kr = t >> 4;
        float m = 0.f;
        #pragma unroll 8
        for (int i = 0; i < 32; ++i)
            m = fmaxf(m, fabsf(sm[(kr + i * 16) * 17 + c]));
        red[kr][c] = m;
    }
    __syncthreads();
    if (t < 16) {
        float m = red[0][t];
        #pragma unroll
        for (int r = 1; r < 16; ++r) m = fmaxf(m, red[r][t]);
        float s = __fdiv_rn(127.0f, fmaxf(m, 1e-7f));
        sscale[t] = s;
        const float A_SCALE = 127.0f / 3.0f;
        g_inv[j0 + t] = __fdiv_rn(1.0f, __fmul_rn(A_SCALE, s));
    }
    __syncthreads();

    const int w = t >> 5, lane = t & 31;
    #pragma unroll
    for (int cc = 0; cc < 2; ++cc) {
        int c = w * 2 + cc;
        float s = sscale[c];
        int kb = lane * 16;
        unsigned pk[4];
        #pragma unroll
        for (int i = 0; i < 4; ++i) {
            int q[4];
            #pragma unroll
            for (int jj = 0; jj < 4; ++jj) {
                float v = __fmul_rn(sm[(kb + i * 4 + jj) * 17 + c], s);
                int qi = __float2int_rn(v);
                q[jj] = max(-127, min(127, qi));
            }
            pk[i] = (q[0] & 0xff) | ((q[1] & 0xff) << 8) |
                    ((q[2] & 0xff) << 16) | ((unsigned)(q[3] & 0xff) << 24);
        }
        *(int4*)&g_wq[(size_t)(j0 + c) * KDIM + kb] =
            make_int4(pk[0], pk[1], pk[2], pk[3]);
    }
}

// ---------------------------------------------------------------------------
// Fused quantize-x + int8 legacy-MMA GEMM, 2 CTAs/SM, double-buffered W.
// ---------------------------------------------------------------------------
__device__ __forceinline__ void load_w_async(uint32_t buf_u, int nb, int t) {
    const int8_t* base = g_wq + (size_t)nb * BN * KDIM;
    #pragma unroll
    for (int i = 0; i < 4; ++i) {
        int idx = i * 256 + t;               // 1024 16B-chunks
        int n = idx >> 5, c16 = idx & 31;
        uint32_t dst = buf_u + n * KDIM + ((c16 * 16) ^ ((n & 7) << 4));
        cp_async16(dst, base + n * KDIM + c16 * 16);
    }
    asm volatile("cp.async.commit_group;" ::: "memory");
}

__global__ void __launch_bounds__(256, 2)
gemm_kernel(const float* __restrict__ x, const float* __restrict__ bias,
            float* __restrict__ y) {
    extern __shared__ char smem[];
    int8_t* xs = (int8_t*)(smem + SM_X);
    int8_t* ws = (int8_t*)(smem + SM_W);
    float* sinv  = (float*)(smem + SM_INV);
    float* sbias = (float*)(smem + SM_BIAS);

    const int t  = threadIdx.x;
    const int r0 = blockIdx.x * BM;
    const uint32_t ws_u = smem_u32(ws);

    // W chunk 0 first: overlaps the x-quant phase
    load_w_async(ws_u, 0, t);

    for (int i = t; i < FDIM; i += 256) {
        sinv[i]  = g_inv[i];
        sbias[i] = bias[i];
    }

    // quantize x tile: 128 x 512 fp32 -> int8, XOR-swizzled rows
    const float A_SCALE = 127.0f / 3.0f;
    #pragma unroll 2
    for (int i = 0; i < 16; ++i) {
        int idx = i * 256 + t;               // 16B-chunk id (4096 total)
        int row = idx >> 5, c16 = idx & 31;
        const float4* src = (const float4*)(x + (size_t)(r0 + row) * KDIM + c16 * 16);
        int pk[4];
        #pragma unroll
        for (int j = 0; j < 4; ++j) {
            float4 v = __ldg(src + j);
            int q0 = max(-127, min(127, __float2int_rn(__fmul_rn(v.x, A_SCALE))));
            int q1 = max(-127, min(127, __float2int_rn(__fmul_rn(v.y, A_SCALE))));
            int q2 = max(-127, min(127, __float2int_rn(__fmul_rn(v.z, A_SCALE))));
            int q3 = max(-127, min(127, __float2int_rn(__fmul_rn(v.w, A_SCALE))));
            pk[j] = (q0 & 0xff) | ((q1 & 0xff) << 8) |
                    ((q2 & 0xff) << 16) | ((unsigned)(q3 & 0xff) << 24);
        }
        *(int4*)&xs[row * KDIM + ((c16 * 16) ^ ((row & 7) << 4))] =
            make_int4(pk[0], pk[1], pk[2], pk[3]);
    }

    const int warp = t >> 5, lane = t & 31;
    const int wm = warp >> 1, wn = warp & 1;     // 4 M-warps x 2 N-warps
    const int grp = lane >> 2, qid = lane & 3;
    const int g4 = grp << 4;

    const int8_t* xr0 = xs + (wm * 32 + grp) * KDIM;   // mt=0 rows grp, grp+8
    const int8_t* xr1 = xr0 + 16 * KDIM;               // mt=1
    float* yr0 = y + (size_t)(r0 + wm * 32 + grp) * FDIM;

    for (int nb = 0; nb < 16; ++nb) {
        // load(nb) was issued a full chunk ago (or in prologue) -> near-zero wait
        asm volatile("cp.async.wait_group 0;" ::: "memory");
        __syncthreads();
        if (nb < 15) load_w_async(ws_u + ((nb + 1) & 1) * WBUF_BYTES, nb + 1, t);

        const int8_t* wr = ws + (nb & 1) * WBUF_BYTES + (wn * 16 + grp) * KDIM;

        int acc[2][2][4];
        #pragma unroll
        for (int mt = 0; mt < 2; ++mt)
            #pragma unroll
            for (int nt = 0; nt < 2; ++nt)
                #pragma unroll
                for (int r = 0; r < 4; ++r) acc[mt][nt][r] = 0;

        #pragma unroll
        for (int ks = 0; ks < 16; ++ks) {
            const int c0 = (ks * 32 + qid * 4) ^ g4;
            const int c1 = (ks * 32 + qid * 4 + 16) ^ g4;
            unsigned a[2][4], b[2][2];
            a[0][0] = *(const unsigned*)(xr0 + c0);
            a[0][1] = *(const unsigned*)(xr0 + 8 * KDIM + c0);
            a[0][2] = *(const unsigned*)(xr0 + c1);
            a[0][3] = *(const unsigned*)(xr0 + 8 * KDIM + c1);
            a[1][0] = *(const unsigned*)(xr1 + c0);
            a[1][1] = *(const unsigned*)(xr1 + 8 * KDIM + c0);
            a[1][2] = *(const unsigned*)(xr1 + c1);
            a[1][3] = *(const unsigned*)(xr1 + 8 * KDIM + c1);
            #pragma unroll
            for (int nt = 0; nt < 2; ++nt) {
                b[nt][0] = *(const unsigned*)(wr + nt * 8 * KDIM + c0);
                b[nt][1] = *(const unsigned*)(wr + nt * 8 * KDIM + c1);
            }
            #pragma unroll
            for (int mt = 0; mt < 2; ++mt)
                #pragma unroll
                for (int nt = 0; nt < 2; ++nt)
                    asm volatile(
                        "mma.sync.aligned.m16n8k32.row.col.s32.s8.s8.s32 "
                        "{%0,%1,%2,%3},{%4,%5,%6,%7},{%8,%9},{%0,%1,%2,%3};\n"
                        : "+r"(acc[mt][nt][0]), "+r"(acc[mt][nt][1]),
                          "+r"(acc[mt][nt][2]), "+r"(acc[mt][nt][3])
                        : "r"(a[mt][0]), "r"(a[mt][1]), "r"(a[mt][2]), "r"(a[mt][3]),
                          "r"(b[nt][0]), "r"(b[nt][1]));
        }

        // epilogue: dequant + bias, float2 stores (no smem-buffer hazards)
        #pragma unroll
        for (int mt = 0; mt < 2; ++mt) {
            float* yr = yr0 + mt * 16 * FDIM;
            #pragma unroll
            for (int nt = 0; nt < 2; ++nt) {
                int col = nb * BN + wn * 16 + nt * 8 + qid * 2;
                float i0 = sinv[col], i1 = sinv[col + 1];
                float b0 = sbias[col], b1 = sbias[col + 1];
                float2 v0, v1;
                v0.x = (float)acc[mt][nt][0] * i0 + b0;
                v0.y = (float)acc[mt][nt][1] * i1 + b1;
                v1.x = (float)acc[mt][nt][2] * i0 + b0;
                v1.y = (float)acc[mt][nt][3] * i1 + b1;
                *(float2*)(yr + col) = v0;
                *(float2*)(yr + 8 * FDIM + col) = v1;
            }
        }
    }
}

// ---------------------------------------------------------------------------
extern "C" void kernel_launch(void* const* d_in, const int* in_sizes, int n_in,
                              void* d_out, int out_size) {
    const float* x    = (const float*)d_in[0];
    const float* kern = (const float*)d_in[1];
    const float* bias = (const float*)d_in[2];
    float* y = (float*)d_out;
    const int nrows = in_sizes[0] / KDIM;

    cudaFuncSetAttribute(gemm_kernel,
                         cudaFuncAttributeMaxDynamicSharedMemorySize, SMEM_TOTAL);

    quant_w_kernel<<<FDIM / 16, 256>>>(kern);
    gemm_kernel<<<nrows / BM, 256, SMEM_TOTAL>>>(x, bias, y);
}